// round 17
// baseline (speedup 1.0000x reference)
#include <cuda_runtime.h>
#include <cuda_fp16.h>
#include <cstdint>
#include <math.h>

#define D_MODEL 768
#define D_FF    2048
#define NE      8
#define T_TOK   2048
#define CAP     2048

// ======================= scratch (__device__ globals) =======================
__device__ int   g_fill[NE];                 // per-expert row count (filled by k_front)
__device__ int   g_rows[NE * CAP];
__device__ float g_wts [NE * CAP];

__device__ __align__(16) __half g_x16[T_TOK * D_MODEL];
// h = silu(g)*u, fp16: [E][CAP][D_FF]
__device__ __align__(16) __half g_h16[(size_t)NE * CAP * D_FF];

// ======================= helpers =======================
__device__ __forceinline__ uint32_t smem_u32(const void* p) {
    uint32_t a;
    asm("{ .reg .u64 t; cvta.to.shared.u64 t, %1; cvt.u32.u64 %0, t; }" : "=r"(a) : "l"(p));
    return a;
}
__device__ __forceinline__ void ldsm4(uint32_t (&r)[4], uint32_t addr) {
    asm volatile("ldmatrix.sync.aligned.m8n8.x4.shared.b16 {%0,%1,%2,%3}, [%4];"
                 : "=r"(r[0]), "=r"(r[1]), "=r"(r[2]), "=r"(r[3]) : "r"(addr));
}
__device__ __forceinline__ void ldsm4t(uint32_t (&r)[4], uint32_t addr) {
    asm volatile("ldmatrix.sync.aligned.m8n8.x4.trans.shared.b16 {%0,%1,%2,%3}, [%4];"
                 : "=r"(r[0]), "=r"(r[1]), "=r"(r[2]), "=r"(r[3]) : "r"(addr));
}
// fp16 inputs, fp32 accumulate
__device__ __forceinline__ void mma16816(float (&d)[4], const uint32_t (&a)[4],
                                         uint32_t b0, uint32_t b1) {
    asm volatile(
        "mma.sync.aligned.m16n8k16.row.col.f32.f16.f16.f32 "
        "{%0,%1,%2,%3}, {%4,%5,%6,%7}, {%8,%9}, {%0,%1,%2,%3};"
        : "+f"(d[0]), "+f"(d[1]), "+f"(d[2]), "+f"(d[3])
        : "r"(a[0]), "r"(a[1]), "r"(a[2]), "r"(a[3]), "r"(b0), "r"(b1));
}

__device__ __forceinline__ uint32_t pack2h(__half a, __half b) {
    __half2 p = __halves2half2(a, b);
    return *reinterpret_cast<uint32_t*>(&p);
}
// 8 fp32 -> 8 fp16, packed as uint4
__device__ __forceinline__ uint4 cvt8h(const float4& f0, const float4& f1) {
    return make_uint4(
        pack2h(__float2half_rn(f0.x), __float2half_rn(f0.y)),
        pack2h(__float2half_rn(f0.z), __float2half_rn(f0.w)),
        pack2h(__float2half_rn(f1.x), __float2half_rn(f1.y)),
        pack2h(__float2half_rn(f1.z), __float2half_rn(f1.w)));
}

// ======================= small kernels =======================
// zero output (vectorized) + per-expert counters
__global__ void k_reset(float* __restrict__ out, int out_n) {
    int i = blockIdx.x * blockDim.x + threadIdx.x;
    if (i < NE) g_fill[i] = 0;
    int n4 = out_n >> 2;
    float4 z4 = make_float4(0.f, 0.f, 0.f, 0.f);
    for (int j = i; j < n4; j += gridDim.x * blockDim.x)
        reinterpret_cast<float4*>(out)[j] = z4;
    for (int j = n4 * 4 + i; j < out_n; j += gridDim.x * blockDim.x)
        out[j] = 0.0f;
}

// fused: router (softmax top-2) + scatter + x fp32->fp16 conversion. One warp/token.
__global__ void k_front(const float* __restrict__ x, const float* __restrict__ gw) {
    int t = blockIdx.x * (blockDim.x >> 5) + (threadIdx.x >> 5);
    int lane = threadIdx.x & 31;
    if (t >= T_TOK) return;
    const float* xr = x + (size_t)t * D_MODEL;
    __half*      xo = g_x16 + (size_t)t * D_MODEL;

    float acc[NE];
#pragma unroll
    for (int e = 0; e < NE; e++) acc[e] = 0.0f;
    for (int d = lane; d < D_MODEL; d += 32) {
        float xv = xr[d];
        xo[d] = __float2half_rn(xv);
        const float* g = gw + (size_t)d * NE;
#pragma unroll
        for (int e = 0; e < NE; e++) acc[e] += xv * g[e];
    }
#pragma unroll
    for (int off = 16; off > 0; off >>= 1)
#pragma unroll
        for (int e = 0; e < NE; e++) acc[e] += __shfl_xor_sync(0xFFFFFFFFu, acc[e], off);

    if (lane == 0) {
        int i0 = 0;
#pragma unroll
        for (int e = 1; e < NE; e++) if (acc[e] > acc[i0]) i0 = e;
        int i1 = -1; float b = -1e30f;
#pragma unroll
        for (int e = 0; e < NE; e++) if (e != i0 && acc[e] > b) { b = acc[e]; i1 = e; }
        float w1 = expf(acc[i1] - acc[i0]);
        float s  = 1.0f + w1;
        int p0 = atomicAdd(&g_fill[i0], 1);
        g_rows[i0 * CAP + p0] = t;  g_wts[i0 * CAP + p0] = 1.0f / s;
        int p1 = atomicAdd(&g_fill[i1], 1);
        g_rows[i1 * CAP + p1] = t;  g_wts[i1 * CAP + p1] = w1 / s;
    }
}

// ======================= HMMA GEMM kernels =======================
// Tile: M=128 x N=64, K-chunk 32. 256 threads = 8 warps in 4(m) x 2(n).
// A smem row stride 40 fp16 (80B), B 72 fp16 (144B) -> ldmatrix conflict-free.
// Grid order: (n-tile, expert, m-tile) — m-tile SLOWEST so live CTAs form one
// contiguous bid prefix, spreading uniformly over SMs (dead CTAs all at tail).
#define SA 40
#define SB 72

// h = silu(x@Wg) * (x@Wu)  (weights read fp32 [k][n] native layout, converted inline)
__global__ void __launch_bounds__(256) k_hmma_gu(
    const float* __restrict__ wg, const float* __restrict__ wu)
{
    int e   = blockIdx.y;
    int cnt = g_fill[e];
    int r0  = blockIdx.z * 128;
    if (r0 >= cnt) return;
    int n0  = blockIdx.x * 64;

    __shared__ __half sA[128 * SA];
    __shared__ __half sGh[32 * SB];
    __shared__ __half sUh[32 * SB];

    int tid = threadIdx.x, lane = tid & 31, wid = tid >> 5;
    int wm = wid >> 1, wn = wid & 1;

    int arow = tid >> 1, ahalf = tid & 1;
    int slotA = r0 + arow;
    int tok = (slotA < cnt) ? g_rows[e * CAP + slotA] : 0;
    const __half* pA = g_x16 + (size_t)tok * D_MODEL + ahalf * 16;
    __half* dA = sA + arow * SA + ahalf * 16;

    int brow = tid >> 3, bq = tid & 7;
    const float* pG = wg + (size_t)e * D_MODEL * D_FF + (size_t)brow * D_FF + n0 + bq * 8;
    const float* pU = wu + (size_t)e * D_MODEL * D_FF + (size_t)brow * D_FF + n0 + bq * 8;
    uint4* dGh = (uint4*)(sGh + brow * SB + bq * 8);
    uint4* dUh = (uint4*)(sUh + brow * SB + bq * 8);

    uint32_t bA  = smem_u32(sA);
    uint32_t bGh = smem_u32(sGh);
    uint32_t bUh = smem_u32(sUh);

    float ag[2][4][4], au[2][4][4];
#pragma unroll
    for (int i = 0; i < 2; i++)
#pragma unroll
        for (int j = 0; j < 4; j++)
#pragma unroll
            for (int q = 0; q < 4; q++) { ag[i][j][q] = 0.0f; au[i][j][q] = 0.0f; }

    for (int c = 0; c < D_MODEL / 32; c++) {      // 24 chunks
        int k0 = c * 32;
        if (c > 0) __syncthreads();
        *(uint4*)dA       = *(const uint4*)(pA + k0);
        *(uint4*)(dA + 8) = *(const uint4*)(pA + k0 + 8);
        {
            const float* s = pG + (size_t)k0 * D_FF;
            float4 f0 = *(const float4*)s, f1 = *(const float4*)(s + 4);
            *dGh = cvt8h(f0, f1);
        }
        {
            const float* s = pU + (size_t)k0 * D_FF;
            float4 f0 = *(const float4*)s, f1 = *(const float4*)(s + 4);
            *dUh = cvt8h(f0, f1);
        }
        __syncthreads();

#pragma unroll
        for (int kk = 0; kk < 32; kk += 16) {
            uint32_t ah[2][4];
#pragma unroll
            for (int mf = 0; mf < 2; mf++) {
                uint32_t ro = wm * 32 + mf * 16 + (lane & 15);
                uint32_t co = kk + (lane >> 4) * 8;
                ldsm4(ah[mf], bA + (ro * SA + co) * 2);
            }
            uint32_t kr = kk + (lane & 7) + ((lane >> 4) & 1) * 8;
            uint32_t ncol = wn * 32 + ((lane >> 3) & 1) * 8;
            {
                uint32_t bh[4][2], r4[4];
#pragma unroll
                for (int p = 0; p < 2; p++) {
                    uint32_t off = (kr * SB + ncol + p * 16) * 2;
                    ldsm4t(r4, bGh + off);
                    bh[p*2][0] = r4[0]; bh[p*2+1][0] = r4[1]; bh[p*2][1] = r4[2]; bh[p*2+1][1] = r4[3];
                }
#pragma unroll
                for (int mf = 0; mf < 2; mf++)
#pragma unroll
                    for (int nf = 0; nf < 4; nf++)
                        mma16816(ag[mf][nf], ah[mf], bh[nf][0], bh[nf][1]);
            }
            {
                uint32_t bh[4][2], r4[4];
#pragma unroll
                for (int p = 0; p < 2; p++) {
                    uint32_t off = (kr * SB + ncol + p * 16) * 2;
                    ldsm4t(r4, bUh + off);
                    bh[p*2][0] = r4[0]; bh[p*2+1][0] = r4[1]; bh[p*2][1] = r4[2]; bh[p*2+1][1] = r4[3];
                }
#pragma unroll
                for (int mf = 0; mf < 2; mf++)
#pragma unroll
                    for (int nf = 0; nf < 4; nf++)
                        mma16816(au[mf][nf], ah[mf], bh[nf][0], bh[nf][1]);
            }
        }
    }

    int lr = lane >> 2, lc = (lane & 3) * 2;
#pragma unroll
    for (int mf = 0; mf < 2; mf++)
#pragma unroll
        for (int half = 0; half < 2; half++) {
            int slot = r0 + wm * 32 + mf * 16 + lr + half * 8;
            if (slot >= cnt) continue;
            size_t base = ((size_t)e * CAP + slot) * D_FF + n0 + wn * 32 + lc;
#pragma unroll
            for (int nf = 0; nf < 4; nf++) {
                float g0 = ag[mf][nf][half * 2 + 0], g1 = ag[mf][nf][half * 2 + 1];
                float u0 = au[mf][nf][half * 2 + 0], u1 = au[mf][nf][half * 2 + 1];
                float h0 = (g0 / (1.0f + __expf(-g0))) * u0;
                float h1 = (g1 / (1.0f + __expf(-g1))) * u1;
                *(__half2*)(g_h16 + base + nf * 8) =
                    __halves2half2(__float2half_rn(h0), __float2half_rn(h1));
            }
        }
}

// out[token] += gate_wt * (h @ Wd)
__global__ void __launch_bounds__(256) k_hmma_down(
    const float* __restrict__ wd, float* __restrict__ out)
{
    int e   = blockIdx.y;
    int cnt = g_fill[e];
    int r0  = blockIdx.z * 128;
    if (r0 >= cnt) return;
    int n0  = blockIdx.x * 64;

    __shared__ __half sA[128 * SA];
    __shared__ __half sBh[32 * SB];

    int tid = threadIdx.x, lane = tid & 31, wid = tid >> 5;
    int wm = wid >> 1, wn = wid & 1;

    int arow = tid >> 1, ahalf = tid & 1;
    int slotA = r0 + arow;
    int asafe = (slotA < cnt) ? slotA : 0;
    size_t hrow = ((size_t)e * CAP + asafe) * D_FF + ahalf * 16;
    const __half* pA = g_h16 + hrow;
    __half* dA = sA + arow * SA + ahalf * 16;

    int brow = tid >> 3, bq = tid & 7;
    const float* pB = wd + (size_t)e * D_FF * D_MODEL + (size_t)brow * D_MODEL + n0 + bq * 8;
    uint4* dBh = (uint4*)(sBh + brow * SB + bq * 8);

    uint32_t bA  = smem_u32(sA);
    uint32_t bBh = smem_u32(sBh);

    float ac[2][4][4];
#pragma unroll
    for (int i = 0; i < 2; i++)
#pragma unroll
        for (int j = 0; j < 4; j++)
#pragma unroll
            for (int q = 0; q < 4; q++) ac[i][j][q] = 0.0f;

    for (int c = 0; c < D_FF / 32; c++) {         // 64 chunks
        int k0 = c * 32;
        if (c > 0) __syncthreads();
        *(uint4*)dA       = *(const uint4*)(pA + k0);
        *(uint4*)(dA + 8) = *(const uint4*)(pA + k0 + 8);
        {
            const float* s = pB + (size_t)k0 * D_MODEL;
            float4 f0 = *(const float4*)s, f1 = *(const float4*)(s + 4);
            *dBh = cvt8h(f0, f1);
        }
        __syncthreads();

#pragma unroll
        for (int kk = 0; kk < 32; kk += 16) {
            uint32_t ah[2][4];
#pragma unroll
            for (int mf = 0; mf < 2; mf++) {
                uint32_t ro = wm * 32 + mf * 16 + (lane & 15);
                uint32_t co = kk + (lane >> 4) * 8;
                ldsm4(ah[mf], bA + (ro * SA + co) * 2);
            }
            uint32_t kr = kk + (lane & 7) + ((lane >> 4) & 1) * 8;
            uint32_t ncol = wn * 32 + ((lane >> 3) & 1) * 8;
            uint32_t bh[4][2], r4[4];
#pragma unroll
            for (int p = 0; p < 2; p++) {
                uint32_t off = (kr * SB + ncol + p * 16) * 2;
                ldsm4t(r4, bBh + off);
                bh[p*2][0] = r4[0]; bh[p*2+1][0] = r4[1]; bh[p*2][1] = r4[2]; bh[p*2+1][1] = r4[3];
            }
#pragma unroll
            for (int mf = 0; mf < 2; mf++)
#pragma unroll
                for (int nf = 0; nf < 4; nf++)
                    mma16816(ac[mf][nf], ah[mf], bh[nf][0], bh[nf][1]);
        }
    }

    // ---- epilogue: weighted atomic scatter-add ----
    int lr = lane >> 2, lc = (lane & 3) * 2;
#pragma unroll
    for (int mf = 0; mf < 2; mf++)
#pragma unroll
        for (int half = 0; half < 2; half++) {
            int slot = r0 + wm * 32 + mf * 16 + lr + half * 8;
            if (slot >= cnt) continue;
            int   tok = g_rows[e * CAP + slot];
            float w   = g_wts [e * CAP + slot];
            float* orow = out + (size_t)tok * D_MODEL + n0 + wn * 32 + lc;
#pragma unroll
            for (int nf = 0; nf < 4; nf++) {
                atomicAdd(&orow[nf * 8 + 0], ac[mf][nf][half * 2 + 0] * w);
                atomicAdd(&orow[nf * 8 + 1], ac[mf][nf][half * 2 + 1] * w);
            }
        }
}

// ======================= launch =======================
extern "C" void kernel_launch(void* const* d_in, const int* in_sizes, int n_in,
                              void* d_out, int out_size) {
    const float* x      = (const float*)d_in[0];   // [2,1024,768]
    const float* gate_w = (const float*)d_in[1];   // [768,8]
    const float* w_gate = (const float*)d_in[2];   // [8,768,2048]
    const float* w_up   = (const float*)d_in[3];   // [8,768,2048]
    const float* w_down = (const float*)d_in[4];   // [8,2048,768]
    float* out = (float*)d_out;

    k_reset<<<512, 256>>>(out, out_size);
    k_front<<<T_TOK / 8, 256>>>(x, gate_w);        // router + scatter + x->fp16

    {   // fused gate/up HMMA + SiLU; grid (n, e, m) — m slowest
        dim3 grid(D_FF / 64, NE, CAP / 128);
        k_hmma_gu<<<grid, 256>>>(w_gate, w_up);
    }
    {   // down HMMA + weighted scatter-add; grid (n, e, m) — m slowest
        dim3 grid(D_MODEL / 64, NE, CAP / 128);
        k_hmma_down<<<grid, 256>>>(w_down, out);
    }
}